// round 1
// baseline (speedup 1.0000x reference)
#include <cuda_runtime.h>
#include <math.h>

// Problem constants
// B=32, C=128, H=W=64, WS=8, SHIFT=4, HEADS=4, TOK=64, NW=64, DH=32, HID=512
#define N_WIN   2048      // B * NW
#define N_TOK   131072    // B * H * W

// ---------------- scratch (device globals; no allocation) ----------------
__device__ float g_q[8192 * 2048];      // [win*4+h][tok=64][d=32]
__device__ float g_k[8192 * 2048];
__device__ float g_v[8192 * 2048];
__device__ float g_attn[N_WIN * 64 * 128];   // [win][tok][c]
__device__ float g_skip[N_TOK * 128];        // [tokg][c], tokg = b*4096 + y*64 + x (orig coords)
__device__ float g_h1[N_TOK * 512];          // [tokg][hid]
__device__ float g_bias[4 * 64 * 64];        // [h][q][k]

// ---------------- 1. meta-MLP relative position bias ----------------
__global__ void bias_kernel(const float* __restrict__ w1, const float* __restrict__ b1,
                            const float* __restrict__ w2, const float* __restrict__ b2) {
    int p = blockIdx.x * 256 + threadIdx.x;      // 16 blocks * 256 = 4096 pairs
    int q = p >> 6, k = p & 63;
    float dy = (float)((q >> 3) - (k >> 3));
    float dx = (float)((q & 7) - (k & 7));
    float r0 = copysignf(log1pf(fabsf(dy)), dy);
    float r1 = copysignf(log1pf(fabsf(dx)), dx);
    float a0 = 0.f, a1 = 0.f, a2 = 0.f, a3 = 0.f;
    for (int j = 0; j < 256; j++) {
        float h = r0 * w1[j] + r1 * w1[256 + j] + b1[j];
        h = fmaxf(h, 0.f);
        a0 += h * w2[j * 4 + 0];
        a1 += h * w2[j * 4 + 1];
        a2 += h * w2[j * 4 + 2];
        a3 += h * w2[j * 4 + 3];
    }
    g_bias[0 * 4096 + p] = a0 + b2[0];
    g_bias[1 * 4096 + p] = a1 + b2[1];
    g_bias[2 * 4096 + p] = a2 + b2[2];
    g_bias[3 * 4096 + p] = a3 + b2[3];
}

// ---------------- 2. fused roll+window gather + QKV GEMM ----------------
// A tile: As[k=c][m=tok] with XOR swizzle; B tile: Bs[k][n] plain.
__global__ void __launch_bounds__(256) qkv_kernel(const float* __restrict__ x,
                                                  const float* __restrict__ w,
                                                  const float* __restrict__ qb) {
    __shared__ float As[128 * 64];   // 32 KB
    __shared__ float Bs[64 * 64];    // 16 KB
    int t = threadIdx.x;
    int win = blockIdx.x;
    int b = win >> 6, wy = (win >> 3) & 7, wx = win & 7;

    // gather x (with -SHIFT roll) into As transposed+swizzled
    for (int it = 0; it < 32; it++) {
        int idx = it * 256 + t;
        int c = idx >> 6, tok = idx & 63;
        int y  = (wy * 8 + (tok >> 3) + 4) & 63;
        int xx = (wx * 8 + (tok & 7) + 4) & 63;
        As[c * 64 + (tok ^ (c & 31))] = x[((b * 128 + c) * 64 + y) * 64 + xx];
    }

    int m0 = (t >> 4) * 4;
    int n0 = (t & 15) * 4;

    for (int nb = 0; nb < 6; nb++) {
        float acc[4][4] = {};
        for (int kb = 0; kb < 2; kb++) {
            __syncthreads();
            for (int it = 0; it < 16; it++) {
                int idx = it * 256 + t;
                int k = idx >> 6, n = idx & 63;
                Bs[k * 64 + n] = w[(kb * 64 + k) * 384 + nb * 64 + n];
            }
            __syncthreads();
#pragma unroll 8
            for (int k = 0; k < 64; k++) {
                int kk = kb * 64 + k;
                int sw = kk & 31;
                float a0 = As[kk * 64 + ((m0 + 0) ^ sw)];
                float a1 = As[kk * 64 + ((m0 + 1) ^ sw)];
                float a2 = As[kk * 64 + ((m0 + 2) ^ sw)];
                float a3 = As[kk * 64 + ((m0 + 3) ^ sw)];
                float4 b4 = *(const float4*)&Bs[k * 64 + n0];
                acc[0][0] += a0 * b4.x; acc[0][1] += a0 * b4.y; acc[0][2] += a0 * b4.z; acc[0][3] += a0 * b4.w;
                acc[1][0] += a1 * b4.x; acc[1][1] += a1 * b4.y; acc[1][2] += a1 * b4.z; acc[1][3] += a1 * b4.w;
                acc[2][0] += a2 * b4.x; acc[2][1] += a2 * b4.y; acc[2][2] += a2 * b4.z; acc[2][3] += a2 * b4.w;
                acc[3][0] += a3 * b4.x; acc[3][1] += a3 * b4.y; acc[3][2] += a3 * b4.z; acc[3][3] += a3 * b4.w;
            }
        }
        int jg = nb * 64 + n0;
        int which = jg >> 7;               // 0=q 1=k 2=v
        int head = (jg >> 5) & 3;
        int d = jg & 31;
        float* dst = (which == 0) ? g_q : (which == 1) ? g_k : g_v;
#pragma unroll
        for (int i = 0; i < 4; i++) {
            float4 v4;
            v4.x = acc[i][0] + qb[jg + 0];
            v4.y = acc[i][1] + qb[jg + 1];
            v4.z = acc[i][2] + qb[jg + 2];
            v4.w = acc[i][3] + qb[jg + 3];
            *(float4*)&dst[((win * 4 + head) * 64 + m0 + i) * 32 + d] = v4;
        }
    }
}

// ---------------- 3. windowed attention (cosine + tau + bias + mask + softmax) ----------------
__global__ void __launch_bounds__(128) attn_kernel(const float* __restrict__ tau) {
    __shared__ float qs[64 * 33];
    __shared__ float ks[64 * 36];
    __shared__ float vs[64 * 36];
    __shared__ float sc[64 * 65];
    __shared__ float qn[64], kn[64];
    __shared__ int   cnti[64];
    __shared__ float stau;

    int t = threadIdx.x;
    int wh = blockIdx.x;                 // win*4 + h
    int win = wh >> 2, h = wh & 3;
    int wy = (win >> 3) & 7, wx = win & 7;

    const float* qp = g_q + (size_t)wh * 2048;
    const float* kp = g_k + (size_t)wh * 2048;
    const float* vp = g_v + (size_t)wh * 2048;

    for (int it = 0; it < 16; it++) {
        int idx = it * 128 + t;
        int tok = idx >> 5, d = idx & 31;
        qs[tok * 33 + d] = qp[idx];
        ks[tok * 36 + d] = kp[idx];
        vs[tok * 36 + d] = vp[idx];
    }
    if (t < 64) {
        int ys = wy * 8 + (t >> 3);
        int xs = wx * 8 + (t & 7);
        int ry = ys < 56 ? 0 : (ys < 60 ? 1 : 2);
        int rx = xs < 56 ? 0 : (xs < 60 ? 1 : 2);
        cnti[t] = ry * 3 + rx;
    }
    if (t == 0) stau = fmaxf(tau[h], 0.01f);
    __syncthreads();

    {   // row norms
        const float* rp = (t < 64) ? &qs[t * 33] : &ks[(t - 64) * 36];
        float s = 0.f;
#pragma unroll
        for (int d = 0; d < 32; d++) s += rp[d] * rp[d];
        float nv = sqrtf(s);
        if (t < 64) qn[t] = nv; else kn[t - 64] = nv;
    }
    __syncthreads();

    int qi = t >> 1;
    int half = t & 1;
    float qreg[32];
#pragma unroll
    for (int d = 0; d < 32; d++) qreg[d] = qs[qi * 33 + d];

    float qnv = qn[qi];
    float tv = stau;
    for (int j = 0; j < 32; j++) {
        int kk = half * 32 + j;
        const float* kr = &ks[kk * 36];
        float s = 0.f;
#pragma unroll
        for (int d4 = 0; d4 < 8; d4++) {
            float4 k4 = *(const float4*)&kr[d4 * 4];
            s += qreg[d4 * 4 + 0] * k4.x + qreg[d4 * 4 + 1] * k4.y
               + qreg[d4 * 4 + 2] * k4.z + qreg[d4 * 4 + 3] * k4.w;
        }
        s = s / fmaxf(qnv * kn[kk], 1e-6f);
        s = s / tv;
        s += g_bias[h * 4096 + qi * 64 + kk];
        if (cnti[qi] != cnti[kk]) s -= 100.f;
        sc[qi * 65 + kk] = s;
    }
    __syncthreads();

    if (t < 64) {   // softmax over row t
        float m = -1e30f;
        for (int kk = 0; kk < 64; kk++) m = fmaxf(m, sc[t * 65 + kk]);
        float sum = 0.f;
        for (int kk = 0; kk < 64; kk++) {
            float e = expf(sc[t * 65 + kk] - m);
            sc[t * 65 + kk] = e;
            sum += e;
        }
        float inv = 1.f / sum;
        for (int kk = 0; kk < 64; kk++) sc[t * 65 + kk] *= inv;
    }
    __syncthreads();

    int d0 = half * 16;
    float acc[16] = {};
    for (int kk = 0; kk < 64; kk++) {
        float a = sc[qi * 65 + kk];
        const float* vr = &vs[kk * 36 + d0];
#pragma unroll
        for (int j4 = 0; j4 < 4; j4++) {
            float4 v4 = *(const float4*)&vr[j4 * 4];
            acc[j4 * 4 + 0] += a * v4.x;
            acc[j4 * 4 + 1] += a * v4.y;
            acc[j4 * 4 + 2] += a * v4.z;
            acc[j4 * 4 + 3] += a * v4.w;
        }
    }
    float* op = g_attn + ((size_t)win * 64 + qi) * 128 + h * 32 + d0;
#pragma unroll
    for (int j4 = 0; j4 < 4; j4++)
        *(float4*)&op[j4 * 4] = make_float4(acc[j4 * 4], acc[j4 * 4 + 1], acc[j4 * 4 + 2], acc[j4 * 4 + 3]);
}

// ---------------- 4. proj GEMM + LN1 + residual -> skip ----------------
__global__ void __launch_bounds__(256) proj_kernel(const float* __restrict__ x,
                                                   const float* __restrict__ w,
                                                   const float* __restrict__ pb,
                                                   const float* __restrict__ lg,
                                                   const float* __restrict__ lb) {
    __shared__ float As[128 * 64];
    __shared__ float Bs[64 * 64];
    int t = threadIdx.x;
    int win = blockIdx.x;
    int b = win >> 6, wy = (win >> 3) & 7, wx = win & 7;

    const float* ap = g_attn + (size_t)win * 8192;
    for (int it = 0; it < 8; it++) {
        int idx = it * 256 + t;
        int tok = idx >> 5, c4 = idx & 31;
        float4 v4 = *(const float4*)&ap[tok * 128 + c4 * 4];
        int c = c4 * 4;
        As[(c + 0) * 64 + (tok ^ ((c + 0) & 31))] = v4.x;
        As[(c + 1) * 64 + (tok ^ ((c + 1) & 31))] = v4.y;
        As[(c + 2) * 64 + (tok ^ ((c + 2) & 31))] = v4.z;
        As[(c + 3) * 64 + (tok ^ ((c + 3) & 31))] = v4.w;
    }

    int m0 = (t >> 4) * 4;
    int n0 = (t & 15) * 4;
    float acc[2][4][4] = {};

    for (int nb = 0; nb < 2; nb++) {
        for (int kb = 0; kb < 2; kb++) {
            __syncthreads();
            for (int it = 0; it < 16; it++) {
                int idx = it * 256 + t;
                int k = idx >> 6, n = idx & 63;
                Bs[k * 64 + n] = w[(kb * 64 + k) * 128 + nb * 64 + n];
            }
            __syncthreads();
#pragma unroll 8
            for (int k = 0; k < 64; k++) {
                int kk = kb * 64 + k;
                int sw = kk & 31;
                float a0 = As[kk * 64 + ((m0 + 0) ^ sw)];
                float a1 = As[kk * 64 + ((m0 + 1) ^ sw)];
                float a2 = As[kk * 64 + ((m0 + 2) ^ sw)];
                float a3 = As[kk * 64 + ((m0 + 3) ^ sw)];
                float4 b4 = *(const float4*)&Bs[k * 64 + n0];
                acc[nb][0][0] += a0 * b4.x; acc[nb][0][1] += a0 * b4.y; acc[nb][0][2] += a0 * b4.z; acc[nb][0][3] += a0 * b4.w;
                acc[nb][1][0] += a1 * b4.x; acc[nb][1][1] += a1 * b4.y; acc[nb][1][2] += a1 * b4.z; acc[nb][1][3] += a1 * b4.w;
                acc[nb][2][0] += a2 * b4.x; acc[nb][2][1] += a2 * b4.y; acc[nb][2][2] += a2 * b4.z; acc[nb][2][3] += a2 * b4.w;
                acc[nb][3][0] += a3 * b4.x; acc[nb][3][1] += a3 * b4.y; acc[nb][3][2] += a3 * b4.z; acc[nb][3][3] += a3 * b4.w;
            }
        }
    }

    // add bias
#pragma unroll
    for (int nb = 0; nb < 2; nb++)
#pragma unroll
        for (int j = 0; j < 4; j++) {
            float bb = pb[nb * 64 + n0 + j];
#pragma unroll
            for (int i = 0; i < 4; i++) acc[nb][i][j] += bb;
        }

    // LN over c per token: 16 lanes (same t>>4 group) cover all 128 channels
    float mu[4], rs[4];
#pragma unroll
    for (int i = 0; i < 4; i++) {
        float s = 0.f, ss = 0.f;
#pragma unroll
        for (int nb = 0; nb < 2; nb++)
#pragma unroll
            for (int j = 0; j < 4; j++) { float v = acc[nb][i][j]; s += v; ss += v * v; }
        for (int o = 8; o; o >>= 1) {
            s  += __shfl_xor_sync(0xffffffffu, s, o);
            ss += __shfl_xor_sync(0xffffffffu, ss, o);
        }
        mu[i] = s * (1.f / 128.f);
        float var = ss * (1.f / 128.f) - mu[i] * mu[i];
        rs[i] = rsqrtf(var + 1e-5f);
    }

    __syncthreads();   // before overwriting As as output-transpose buffer
#pragma unroll
    for (int nb = 0; nb < 2; nb++)
#pragma unroll
        for (int i = 0; i < 4; i++)
#pragma unroll
            for (int j = 0; j < 4; j++) {
                int c = nb * 64 + n0 + j;
                int tok = m0 + i;
                As[c * 64 + (tok ^ (c & 31))] =
                    (acc[nb][i][j] - mu[i]) * rs[i] * lg[c] + lb[c];
            }
    __syncthreads();

    // add residual x (orig coords) and write skip token-major
    for (int it = 0; it < 32; it++) {
        int idx = it * 256 + t;
        int tok = idx >> 7, c = idx & 127;
        int ys = wy * 8 + (tok >> 3), xs = wx * 8 + (tok & 7);
        int y = (ys + 4) & 63, xx = (xs + 4) & 63;
        float v = As[c * 64 + (tok ^ (c & 31))] + x[((b * 128 + c) * 64 + y) * 64 + xx];
        g_skip[((size_t)b * 4096 + y * 64 + xx) * 128 + c] = v;
    }
}

// ---------------- 5. FFN1 GEMM + exact GELU -> h1 ----------------
__global__ void __launch_bounds__(256) ffn1_kernel(const float* __restrict__ w,
                                                   const float* __restrict__ b1) {
    __shared__ float As[128 * 64];
    __shared__ float Bs[64 * 64];
    int t = threadIdx.x;
    int tile = blockIdx.x;                // 64 consecutive tokens
    const float* sp = g_skip + (size_t)tile * 64 * 128;

    for (int it = 0; it < 8; it++) {
        int idx = it * 256 + t;
        int tok = idx >> 5, c4 = idx & 31;
        float4 v4 = *(const float4*)&sp[tok * 128 + c4 * 4];
        int c = c4 * 4;
        As[(c + 0) * 64 + (tok ^ ((c + 0) & 31))] = v4.x;
        As[(c + 1) * 64 + (tok ^ ((c + 1) & 31))] = v4.y;
        As[(c + 2) * 64 + (tok ^ ((c + 2) & 31))] = v4.z;
        As[(c + 3) * 64 + (tok ^ ((c + 3) & 31))] = v4.w;
    }

    int m0 = (t >> 4) * 4;
    int n0 = (t & 15) * 4;

    for (int nb = 0; nb < 8; nb++) {
        float acc[4][4] = {};
        for (int kb = 0; kb < 2; kb++) {
            __syncthreads();
            for (int it = 0; it < 16; it++) {
                int idx = it * 256 + t;
                int k = idx >> 6, n = idx & 63;
                Bs[k * 64 + n] = w[(kb * 64 + k) * 512 + nb * 64 + n];
            }
            __syncthreads();
#pragma unroll 8
            for (int k = 0; k < 64; k++) {
                int kk = kb * 64 + k;
                int sw = kk & 31;
                float a0 = As[kk * 64 + ((m0 + 0) ^ sw)];
                float a1 = As[kk * 64 + ((m0 + 1) ^ sw)];
                float a2 = As[kk * 64 + ((m0 + 2) ^ sw)];
                float a3 = As[kk * 64 + ((m0 + 3) ^ sw)];
                float4 b4 = *(const float4*)&Bs[k * 64 + n0];
                acc[0][0] += a0 * b4.x; acc[0][1] += a0 * b4.y; acc[0][2] += a0 * b4.z; acc[0][3] += a0 * b4.w;
                acc[1][0] += a1 * b4.x; acc[1][1] += a1 * b4.y; acc[1][2] += a1 * b4.z; acc[1][3] += a1 * b4.w;
                acc[2][0] += a2 * b4.x; acc[2][1] += a2 * b4.y; acc[2][2] += a2 * b4.z; acc[2][3] += a2 * b4.w;
                acc[3][0] += a3 * b4.x; acc[3][1] += a3 * b4.y; acc[3][2] += a3 * b4.z; acc[3][3] += a3 * b4.w;
            }
        }
#pragma unroll
        for (int i = 0; i < 4; i++) {
            float4 v4;
            float* pv = (float*)&v4;
#pragma unroll
            for (int j = 0; j < 4; j++) {
                float v = acc[i][j] + b1[nb * 64 + n0 + j];
                pv[j] = 0.5f * v * (1.f + erff(v * 0.70710678118654752f));
            }
            *(float4*)&g_h1[((size_t)tile * 64 + m0 + i) * 512 + nb * 64 + n0] = v4;
        }
    }
}

// ---------------- 6. FFN2 GEMM (K=512) + LN2 + residual -> out [B,C,H,W] ----------------
__global__ void __launch_bounds__(256) ffn2_kernel(const float* __restrict__ w,
                                                   const float* __restrict__ b2,
                                                   const float* __restrict__ lg,
                                                   const float* __restrict__ lb,
                                                   float* __restrict__ out) {
    __shared__ float As[128 * 64];
    __shared__ float Bs[64 * 64];
    int t = threadIdx.x;
    int tile = blockIdx.x;

    int m0 = (t >> 4) * 4;
    int n0 = (t & 15) * 4;
    float acc[2][4][4] = {};

    for (int kb = 0; kb < 4; kb++) {
        __syncthreads();
        const float* hp = g_h1 + (size_t)tile * 64 * 512 + kb * 128;
        for (int it = 0; it < 8; it++) {
            int idx = it * 256 + t;
            int tok = idx >> 5, k4 = idx & 31;
            float4 v4 = *(const float4*)&hp[tok * 512 + k4 * 4];
            int k = k4 * 4;
            As[(k + 0) * 64 + (tok ^ ((k + 0) & 31))] = v4.x;
            As[(k + 1) * 64 + (tok ^ ((k + 1) & 31))] = v4.y;
            As[(k + 2) * 64 + (tok ^ ((k + 2) & 31))] = v4.z;
            As[(k + 3) * 64 + (tok ^ ((k + 3) & 31))] = v4.w;
        }
        for (int kb2 = 0; kb2 < 2; kb2++) {
            for (int nb = 0; nb < 2; nb++) {
                __syncthreads();
                for (int it = 0; it < 16; it++) {
                    int idx = it * 256 + t;
                    int k = idx >> 6, n = idx & 63;
                    Bs[k * 64 + n] = w[(kb * 128 + kb2 * 64 + k) * 128 + nb * 64 + n];
                }
                __syncthreads();
#pragma unroll 8
                for (int k = 0; k < 64; k++) {
                    int kk = kb2 * 64 + k;
                    int sw = kk & 31;
                    float a0 = As[kk * 64 + ((m0 + 0) ^ sw)];
                    float a1 = As[kk * 64 + ((m0 + 1) ^ sw)];
                    float a2 = As[kk * 64 + ((m0 + 2) ^ sw)];
                    float a3 = As[kk * 64 + ((m0 + 3) ^ sw)];
                    float4 b4 = *(const float4*)&Bs[k * 64 + n0];
                    acc[nb][0][0] += a0 * b4.x; acc[nb][0][1] += a0 * b4.y; acc[nb][0][2] += a0 * b4.z; acc[nb][0][3] += a0 * b4.w;
                    acc[nb][1][0] += a1 * b4.x; acc[nb][1][1] += a1 * b4.y; acc[nb][1][2] += a1 * b4.z; acc[nb][1][3] += a1 * b4.w;
                    acc[nb][2][0] += a2 * b4.x; acc[nb][2][1] += a2 * b4.y; acc[nb][2][2] += a2 * b4.z; acc[nb][2][3] += a2 * b4.w;
                    acc[nb][3][0] += a3 * b4.x; acc[nb][3][1] += a3 * b4.y; acc[nb][3][2] += a3 * b4.z; acc[nb][3][3] += a3 * b4.w;
                }
            }
        }
    }

    // add b2
#pragma unroll
    for (int nb = 0; nb < 2; nb++)
#pragma unroll
        for (int j = 0; j < 4; j++) {
            float bb = b2[nb * 64 + n0 + j];
#pragma unroll
            for (int i = 0; i < 4; i++) acc[nb][i][j] += bb;
        }

    // LN2 per token via 16-lane shfl
    float mu[4], rs[4];
#pragma unroll
    for (int i = 0; i < 4; i++) {
        float s = 0.f, ss = 0.f;
#pragma unroll
        for (int nb = 0; nb < 2; nb++)
#pragma unroll
            for (int j = 0; j < 4; j++) { float v = acc[nb][i][j]; s += v; ss += v * v; }
        for (int o = 8; o; o >>= 1) {
            s  += __shfl_xor_sync(0xffffffffu, s, o);
            ss += __shfl_xor_sync(0xffffffffu, ss, o);
        }
        mu[i] = s * (1.f / 128.f);
        float var = ss * (1.f / 128.f) - mu[i] * mu[i];
        rs[i] = rsqrtf(var + 1e-5f);
    }

    __syncthreads();
    // normalized + residual -> As (transposed, swizzled)
#pragma unroll
    for (int i = 0; i < 4; i++) {
        int tok = m0 + i;
        const float* skp = &g_skip[((size_t)tile * 64 + tok) * 128];
#pragma unroll
        for (int nb = 0; nb < 2; nb++) {
            float4 s4 = *(const float4*)&skp[nb * 64 + n0];
            const float* ps = (const float*)&s4;
#pragma unroll
            for (int j = 0; j < 4; j++) {
                int c = nb * 64 + n0 + j;
                As[c * 64 + (tok ^ (c & 31))] =
                    (acc[nb][i][j] - mu[i]) * rs[i] * lg[c] + lb[c] + ps[j];
            }
        }
    }
    __syncthreads();

    // write out [B,C,H,W]: tile = b*64 + y, tok = x -> contiguous 256B per (c,y)
    int b = tile >> 6, y = tile & 63;
    for (int it = 0; it < 32; it++) {
        int idx = it * 256 + t;
        int c = idx >> 6, tok = idx & 63;
        out[((b * 128 + c) * 64 + y) * 64 + tok] = As[c * 64 + (tok ^ (c & 31))];
    }
}

// ---------------- launch ----------------
extern "C" void kernel_launch(void* const* d_in, const int* in_sizes, int n_in,
                              void* d_out, int out_size) {
    (void)in_sizes; (void)n_in; (void)out_size;
    const float* x      = (const float*)d_in[0];
    const float* qkv_w  = (const float*)d_in[1];
    const float* qkv_b  = (const float*)d_in[2];
    const float* proj_w = (const float*)d_in[3];
    const float* proj_b = (const float*)d_in[4];
    const float* mw1    = (const float*)d_in[5];
    const float* mb1    = (const float*)d_in[6];
    const float* mw2    = (const float*)d_in[7];
    const float* mb2    = (const float*)d_in[8];
    const float* tau    = (const float*)d_in[9];
    const float* ln1_g  = (const float*)d_in[10];
    const float* ln1_b  = (const float*)d_in[11];
    const float* ln2_g  = (const float*)d_in[12];
    const float* ln2_b  = (const float*)d_in[13];
    const float* ffn_w1 = (const float*)d_in[14];
    const float* ffn_b1 = (const float*)d_in[15];
    const float* ffn_w2 = (const float*)d_in[16];
    const float* ffn_b2 = (const float*)d_in[17];
    float* out = (float*)d_out;

    bias_kernel<<<16, 256>>>(mw1, mb1, mw2, mb2);
    qkv_kernel<<<N_WIN, 256>>>(x, qkv_w, qkv_b);
    attn_kernel<<<8192, 128>>>(tau);
    proj_kernel<<<N_WIN, 256>>>(x, proj_w, proj_b, ln1_g, ln1_b);
    ffn1_kernel<<<2048, 256>>>(ffn_w1, ffn_b1);
    ffn2_kernel<<<2048, 256>>>(ffn_w2, ffn_b2, ln2_g, ln2_b, out);
}

// round 2
// speedup vs baseline: 2.1587x; 2.1587x over previous
#include <cuda_runtime.h>
#include <math.h>
#include <stdint.h>

// Problem constants: B=32, C=128, H=W=64, WS=8, SHIFT=4, HEADS=4, TOK=64, NW=64, DH=32, HID=512
#define N_WIN   2048      // B * NW
#define N_TOK   131072    // B * H * W

// ---------------- scratch (device globals; no allocation) ----------------
__device__ float g_xw[N_WIN * 64 * 128];     // rolled+windowed x, token-major
__device__ float g_q[8192 * 2048];           // [win*4+h][tok=64][d=32]
__device__ float g_k[8192 * 2048];
__device__ float g_v[8192 * 2048];
__device__ float g_attn[N_WIN * 64 * 128];   // [win][tok][c]
__device__ float g_skip[N_TOK * 128];        // [tokg][c], tokg = b*4096 + y*64 + x (orig coords)
__device__ float g_h1[N_TOK * 512];          // [tokg][hid]
__device__ float g_bias[4 * 64 * 64];        // [h][q][k]

// ---------------- tf32 mma helpers ----------------
__device__ __forceinline__ uint32_t f2tf32(float x) {
    uint32_t r;
    asm("cvt.rna.tf32.f32 %0, %1;" : "=r"(r) : "f"(x));
    return r;
}

__device__ __forceinline__ void mma8(float c[4], uint32_t a0, uint32_t a1, uint32_t a2, uint32_t a3,
                                     uint32_t b0, uint32_t b1) {
    asm volatile("mma.sync.aligned.m16n8k8.row.col.f32.tf32.tf32.f32 "
                 "{%0,%1,%2,%3},{%4,%5,%6,%7},{%8,%9},{%0,%1,%2,%3};"
                 : "+f"(c[0]), "+f"(c[1]), "+f"(c[2]), "+f"(c[3])
                 : "r"(a0), "r"(a1), "r"(a2), "r"(a3), "r"(b0), "r"(b1));
}

// Block tile: M=64, N=128, K-chunk=32. 8 warps = 4(M) x 2(N); warp tile 16x64.
// As layout [m][36] (pad 4): fragment loads conflict-free (bank = 4g+tg).
// Bs layout [k][136] (pad 8): fragment loads conflict-free (bank = 8tg+g).
template<int KTOT, int NTOT>
__device__ __forceinline__ void gemm64x128(const float* __restrict__ A,   // [64][KTOT] row-major
                                           const float* __restrict__ W,   // [KTOT][NTOT] row-major
                                           int nbase,
                                           uint32_t* As, uint32_t* Bs,
                                           float acc[8][4], int t) {
    const int lane = t & 31, g = lane >> 2, tg = lane & 3;
    const int wm = (t >> 5) & 3, wn = t >> 7;
    const int m0w = wm * 16, n0w = wn * 64;

    for (int k0 = 0; k0 < KTOT; k0 += 32) {
        __syncthreads();
#pragma unroll
        for (int it = 0; it < 2; it++) {      // A chunk: 64m x 32k
            int p = it * 256 + t;
            int m = p >> 3, k4 = p & 7;
            float4 v = *(const float4*)&A[m * KTOT + k0 + k4 * 4];
            uint4 u = make_uint4(f2tf32(v.x), f2tf32(v.y), f2tf32(v.z), f2tf32(v.w));
            *(uint4*)&As[m * 36 + k4 * 4] = u;
        }
#pragma unroll
        for (int it = 0; it < 4; it++) {      // B chunk: 32k x 128n
            int p = it * 256 + t;
            int k = p >> 5, n4 = p & 31;
            float4 v = *(const float4*)&W[(size_t)(k0 + k) * NTOT + nbase + n4 * 4];
            uint4 u = make_uint4(f2tf32(v.x), f2tf32(v.y), f2tf32(v.z), f2tf32(v.w));
            *(uint4*)&Bs[k * 136 + n4 * 4] = u;
        }
        __syncthreads();
#pragma unroll
        for (int ks = 0; ks < 4; ks++) {
            int kk = ks * 8;
            uint32_t a0 = As[(m0w + g) * 36 + kk + tg];
            uint32_t a1 = As[(m0w + g + 8) * 36 + kk + tg];
            uint32_t a2 = As[(m0w + g) * 36 + kk + tg + 4];
            uint32_t a3 = As[(m0w + g + 8) * 36 + kk + tg + 4];
#pragma unroll
            for (int s = 0; s < 8; s++) {
                uint32_t b0 = Bs[(kk + tg) * 136 + n0w + s * 8 + g];
                uint32_t b1 = Bs[(kk + tg + 4) * 136 + n0w + s * 8 + g];
                mma8(acc[s], a0, a1, a2, a3, b0, b1);
            }
        }
    }
}

#define SMEM_BYTES 33792   // max( As 9216 + Bs 17408 = 26624 , Cs 64*132*4 = 33792 )

// ---------------- 0. meta-MLP relative position bias ----------------
__global__ void bias_kernel(const float* __restrict__ w1, const float* __restrict__ b1,
                            const float* __restrict__ w2, const float* __restrict__ b2) {
    int p = blockIdx.x * 256 + threadIdx.x;      // 4096 pairs
    int q = p >> 6, k = p & 63;
    float dy = (float)((q >> 3) - (k >> 3));
    float dx = (float)((q & 7) - (k & 7));
    float r0 = copysignf(log1pf(fabsf(dy)), dy);
    float r1 = copysignf(log1pf(fabsf(dx)), dx);
    float a0 = 0.f, a1 = 0.f, a2 = 0.f, a3 = 0.f;
    for (int j = 0; j < 256; j++) {
        float h = r0 * w1[j] + r1 * w1[256 + j] + b1[j];
        h = fmaxf(h, 0.f);
        a0 += h * w2[j * 4 + 0];
        a1 += h * w2[j * 4 + 1];
        a2 += h * w2[j * 4 + 2];
        a3 += h * w2[j * 4 + 3];
    }
    g_bias[0 * 4096 + p] = a0 + b2[0];
    g_bias[1 * 4096 + p] = a1 + b2[1];
    g_bias[2 * 4096 + p] = a2 + b2[2];
    g_bias[3 * 4096 + p] = a3 + b2[3];
}

// ---------------- 1. roll + window gather -> g_xw (token-major) ----------------
__global__ void __launch_bounds__(256) gather_kernel(const float* __restrict__ x) {
    __shared__ __align__(16) float Ts[64 * 132];
    int t = threadIdx.x;
    int win = blockIdx.x;
    int b = win >> 6, wy = (win >> 3) & 7, wx = win & 7;

    // read: (c, row, half) -> float4 along xx (never straddles the 4-aligned wrap)
    for (int it = 0; it < 8; it++) {
        int p = it * 256 + t;                // 2048 tasks
        int c = p >> 4;
        int r = (p >> 1) & 7;
        int half = p & 1;
        int y = (wy * 8 + r + 4) & 63;
        int xb = (wx * 8 + 4 + half * 4) & 63;
        float4 v = *(const float4*)&x[((size_t)(b * 128 + c) * 64 + y) * 64 + xb];
        int tok = r * 8 + half * 4;
        Ts[(tok + 0) * 132 + c] = v.x;
        Ts[(tok + 1) * 132 + c] = v.y;
        Ts[(tok + 2) * 132 + c] = v.z;
        Ts[(tok + 3) * 132 + c] = v.w;
    }
    __syncthreads();
    float* dst = g_xw + (size_t)win * 64 * 128;
    for (int it = 0; it < 8; it++) {
        int p = it * 256 + t;                // 2048 float4
        int tok = p >> 5, c4 = p & 31;
        *(float4*)&dst[tok * 128 + c4 * 4] = *(const float4*)&Ts[tok * 132 + c4 * 4];
    }
}

// ---------------- 2. QKV GEMM (tf32 mma) ----------------
__global__ void __launch_bounds__(256) qkv_mma(const float* __restrict__ w,
                                               const float* __restrict__ qb) {
    __shared__ __align__(16) unsigned char smbuf[SMEM_BYTES];
    uint32_t* As = (uint32_t*)smbuf;
    uint32_t* Bs = As + 64 * 36;
    int t = threadIdx.x;
    int tile = blockIdx.x;          // window
    int nby = blockIdx.y;           // 0=q 1=k 2=v

    float acc[8][4] = {};
    gemm64x128<128, 384>(g_xw + (size_t)tile * 64 * 128, w, nby * 128, As, Bs, acc, t);

    const int lane = t & 31, g = lane >> 2, tg = lane & 3;
    const int wm = (t >> 5) & 3, wn = t >> 7;
    const int m0w = wm * 16, n0w = wn * 64;
    float* dst = (nby == 0) ? g_q : (nby == 1) ? g_k : g_v;
#pragma unroll
    for (int s = 0; s < 8; s++) {
        int nl = n0w + s * 8 + 2 * tg;
        int head = nl >> 5, d = nl & 31;
        float b0v = qb[nby * 128 + nl], b1v = qb[nby * 128 + nl + 1];
        int m = m0w + g;
        float* base = &dst[((size_t)(tile * 4 + head) * 64 + m) * 32 + d];
        *(float2*)base = make_float2(acc[s][0] + b0v, acc[s][1] + b1v);
        *(float2*)(base + 8 * 32) = make_float2(acc[s][2] + b0v, acc[s][3] + b1v);
    }
}

// ---------------- 3. windowed attention ----------------
__global__ void __launch_bounds__(128) attn_kernel(const float* __restrict__ tau) {
    __shared__ float qs[64 * 33];
    __shared__ float ks[64 * 36];
    __shared__ float vs[64 * 36];
    __shared__ float sc[64 * 65];
    __shared__ float qn[64], kn[64];
    __shared__ int   cnti[64];
    __shared__ float stau;

    int t = threadIdx.x;
    int wh = blockIdx.x;                 // win*4 + h
    int win = wh >> 2, h = wh & 3;
    int wy = (win >> 3) & 7, wx = win & 7;

    const float* qp = g_q + (size_t)wh * 2048;
    const float* kp = g_k + (size_t)wh * 2048;
    const float* vp = g_v + (size_t)wh * 2048;

    for (int it = 0; it < 16; it++) {
        int idx = it * 128 + t;
        int tok = idx >> 5, d = idx & 31;
        qs[tok * 33 + d] = qp[idx];
        ks[tok * 36 + d] = kp[idx];
        vs[tok * 36 + d] = vp[idx];
    }
    if (t < 64) {
        int ys = wy * 8 + (t >> 3);
        int xs = wx * 8 + (t & 7);
        int ry = ys < 56 ? 0 : (ys < 60 ? 1 : 2);
        int rx = xs < 56 ? 0 : (xs < 60 ? 1 : 2);
        cnti[t] = ry * 3 + rx;
    }
    if (t == 0) stau = fmaxf(tau[h], 0.01f);
    __syncthreads();

    {   // row norms
        const float* rp = (t < 64) ? &qs[t * 33] : &ks[(t - 64) * 36];
        float s = 0.f;
#pragma unroll
        for (int d = 0; d < 32; d++) s += rp[d] * rp[d];
        float nv = sqrtf(s);
        if (t < 64) qn[t] = nv; else kn[t - 64] = nv;
    }
    __syncthreads();

    int qi = t >> 1;
    int half = t & 1;
    float qreg[32];
#pragma unroll
    for (int d = 0; d < 32; d++) qreg[d] = qs[qi * 33 + d];

    float qnv = qn[qi];
    float tv = stau;
    for (int j = 0; j < 32; j++) {
        int kk = half * 32 + j;
        const float* kr = &ks[kk * 36];
        float s = 0.f;
#pragma unroll
        for (int d4 = 0; d4 < 8; d4++) {
            float4 k4 = *(const float4*)&kr[d4 * 4];
            s += qreg[d4 * 4 + 0] * k4.x + qreg[d4 * 4 + 1] * k4.y
               + qreg[d4 * 4 + 2] * k4.z + qreg[d4 * 4 + 3] * k4.w;
        }
        s = s / fmaxf(qnv * kn[kk], 1e-6f);
        s = s / tv;
        s += g_bias[h * 4096 + qi * 64 + kk];
        if (cnti[qi] != cnti[kk]) s -= 100.f;
        sc[qi * 65 + kk] = s;
    }
    __syncthreads();

    if (t < 64) {
        float m = -1e30f;
        for (int kk = 0; kk < 64; kk++) m = fmaxf(m, sc[t * 65 + kk]);
        float sum = 0.f;
        for (int kk = 0; kk < 64; kk++) {
            float e = expf(sc[t * 65 + kk] - m);
            sc[t * 65 + kk] = e;
            sum += e;
        }
        float inv = 1.f / sum;
        for (int kk = 0; kk < 64; kk++) sc[t * 65 + kk] *= inv;
    }
    __syncthreads();

    int d0 = half * 16;
    float acc[16] = {};
    for (int kk = 0; kk < 64; kk++) {
        float a = sc[qi * 65 + kk];
        const float* vr = &vs[kk * 36 + d0];
#pragma unroll
        for (int j4 = 0; j4 < 4; j4++) {
            float4 v4 = *(const float4*)&vr[j4 * 4];
            acc[j4 * 4 + 0] += a * v4.x;
            acc[j4 * 4 + 1] += a * v4.y;
            acc[j4 * 4 + 2] += a * v4.z;
            acc[j4 * 4 + 3] += a * v4.w;
        }
    }
    float* op = g_attn + ((size_t)win * 64 + qi) * 128 + h * 32 + d0;
#pragma unroll
    for (int j4 = 0; j4 < 4; j4++)
        *(float4*)&op[j4 * 4] = make_float4(acc[j4 * 4], acc[j4 * 4 + 1], acc[j4 * 4 + 2], acc[j4 * 4 + 3]);
}

// ---------------- 4. proj (tf32 mma) + LN1 + residual -> g_skip ----------------
__global__ void __launch_bounds__(256) proj_mma(const float* __restrict__ x,
                                                const float* __restrict__ w,
                                                const float* __restrict__ pb,
                                                const float* __restrict__ lg,
                                                const float* __restrict__ lb) {
    __shared__ __align__(16) unsigned char smbuf[SMEM_BYTES];
    uint32_t* As = (uint32_t*)smbuf;
    uint32_t* Bs = As + 64 * 36;
    float* Cs = (float*)smbuf;
    int t = threadIdx.x;
    int win = blockIdx.x;
    int b = win >> 6, wy = (win >> 3) & 7, wx = win & 7;

    float acc[8][4] = {};
    gemm64x128<128, 128>(g_attn + (size_t)win * 64 * 128, w, 0, As, Bs, acc, t);

    const int lane = t & 31, g = lane >> 2, tg = lane & 3;
    const int wm = (t >> 5) & 3, wn = t >> 7;
    const int m0w = wm * 16, n0w = wn * 64;

    __syncthreads();
#pragma unroll
    for (int s = 0; s < 8; s++) {
        int c = n0w + s * 8 + 2 * tg;
        float b0v = pb[c], b1v = pb[c + 1];
        Cs[(m0w + g) * 132 + c]       = acc[s][0] + b0v;
        Cs[(m0w + g) * 132 + c + 1]   = acc[s][1] + b1v;
        Cs[(m0w + g + 8) * 132 + c]     = acc[s][2] + b0v;
        Cs[(m0w + g + 8) * 132 + c + 1] = acc[s][3] + b1v;
    }
    __syncthreads();

    // LN + residual + store (warp w handles tokens w*8..w*8+7)
    int wrp = t >> 5;
    float4 lg4 = *(const float4*)&lg[lane * 4];
    float4 lb4 = *(const float4*)&lb[lane * 4];
    for (int i = 0; i < 8; i++) {
        int tk = wrp * 8 + i;
        float4 v = *(const float4*)&Cs[tk * 132 + lane * 4];
        float s  = v.x + v.y + v.z + v.w;
        float ss = v.x * v.x + v.y * v.y + v.z * v.z + v.w * v.w;
#pragma unroll
        for (int o = 16; o; o >>= 1) {
            s  += __shfl_xor_sync(0xffffffffu, s, o);
            ss += __shfl_xor_sync(0xffffffffu, ss, o);
        }
        float mu = s * (1.f / 128.f);
        float var = ss * (1.f / 128.f) - mu * mu;
        float rs = rsqrtf(var + 1e-5f);

        int y  = (wy * 8 + (tk >> 3) + 4) & 63;
        int xx = (wx * 8 + (tk & 7) + 4) & 63;
        const float* xr = x + ((size_t)(b * 128 + lane * 4) * 64 + y) * 64 + xx;
        float4 o4;
        o4.x = (v.x - mu) * rs * lg4.x + lb4.x + xr[0];
        o4.y = (v.y - mu) * rs * lg4.y + lb4.y + xr[4096];
        o4.z = (v.z - mu) * rs * lg4.z + lb4.z + xr[8192];
        o4.w = (v.w - mu) * rs * lg4.w + lb4.w + xr[12288];
        *(float4*)&g_skip[((size_t)b * 4096 + y * 64 + xx) * 128 + lane * 4] = o4;
    }
}

// ---------------- 5. FFN1 (tf32 mma) + GELU -> g_h1 ----------------
__global__ void __launch_bounds__(256) ffn1_mma(const float* __restrict__ w,
                                                const float* __restrict__ b1) {
    __shared__ __align__(16) unsigned char smbuf[SMEM_BYTES];
    uint32_t* As = (uint32_t*)smbuf;
    uint32_t* Bs = As + 64 * 36;
    int t = threadIdx.x;
    int tile = blockIdx.x;
    int nby = blockIdx.y;

    float acc[8][4] = {};
    gemm64x128<128, 512>(g_skip + (size_t)tile * 64 * 128, w, nby * 128, As, Bs, acc, t);

    const int lane = t & 31, g = lane >> 2, tg = lane & 3;
    const int wm = (t >> 5) & 3, wn = t >> 7;
    const int m0w = wm * 16, n0w = wn * 64;
#pragma unroll
    for (int s = 0; s < 8; s++) {
        int nl = n0w + s * 8 + 2 * tg;
        int ng = nby * 128 + nl;
        float b0v = b1[ng], b1v = b1[ng + 1];
        int m = m0w + g;
        float h0 = acc[s][0] + b0v, h1 = acc[s][1] + b1v;
        float h2 = acc[s][2] + b0v, h3 = acc[s][3] + b1v;
        h0 = 0.5f * h0 * (1.f + erff(h0 * 0.70710678118654752f));
        h1 = 0.5f * h1 * (1.f + erff(h1 * 0.70710678118654752f));
        h2 = 0.5f * h2 * (1.f + erff(h2 * 0.70710678118654752f));
        h3 = 0.5f * h3 * (1.f + erff(h3 * 0.70710678118654752f));
        float* base = &g_h1[((size_t)tile * 64 + m) * 512 + ng];
        *(float2*)base = make_float2(h0, h1);
        *(float2*)(base + 8 * 512) = make_float2(h2, h3);
    }
}

// ---------------- 6. FFN2 (tf32 mma, K=512) + LN2 + residual -> out [B,C,H,W] ----------------
__global__ void __launch_bounds__(256) ffn2_mma(const float* __restrict__ w,
                                                const float* __restrict__ b2,
                                                const float* __restrict__ lg,
                                                const float* __restrict__ lb,
                                                float* __restrict__ out) {
    __shared__ __align__(16) unsigned char smbuf[SMEM_BYTES];
    uint32_t* As = (uint32_t*)smbuf;
    uint32_t* Bs = As + 64 * 36;
    float* Cs = (float*)smbuf;
    int t = threadIdx.x;
    int tile = blockIdx.x;

    float acc[8][4] = {};
    gemm64x128<512, 128>(g_h1 + (size_t)tile * 64 * 512, w, 0, As, Bs, acc, t);

    const int lane = t & 31, g = lane >> 2, tg = lane & 3;
    const int wm = (t >> 5) & 3, wn = t >> 7;
    const int m0w = wm * 16, n0w = wn * 64;

    __syncthreads();
#pragma unroll
    for (int s = 0; s < 8; s++) {
        int c = n0w + s * 8 + 2 * tg;
        float b0v = b2[c], b1v = b2[c + 1];
        Cs[(m0w + g) * 132 + c]         = acc[s][0] + b0v;
        Cs[(m0w + g) * 132 + c + 1]     = acc[s][1] + b1v;
        Cs[(m0w + g + 8) * 132 + c]     = acc[s][2] + b0v;
        Cs[(m0w + g + 8) * 132 + c + 1] = acc[s][3] + b1v;
    }
    __syncthreads();

    // LN2 + residual, back into Cs
    int wrp = t >> 5;
    float4 lg4 = *(const float4*)&lg[lane * 4];
    float4 lb4 = *(const float4*)&lb[lane * 4];
    for (int i = 0; i < 8; i++) {
        int tk = wrp * 8 + i;
        float4 v = *(const float4*)&Cs[tk * 132 + lane * 4];
        float s  = v.x + v.y + v.z + v.w;
        float ss = v.x * v.x + v.y * v.y + v.z * v.z + v.w * v.w;
#pragma unroll
        for (int o = 16; o; o >>= 1) {
            s  += __shfl_xor_sync(0xffffffffu, s, o);
            ss += __shfl_xor_sync(0xffffffffu, ss, o);
        }
        float mu = s * (1.f / 128.f);
        float var = ss * (1.f / 128.f) - mu * mu;
        float rs = rsqrtf(var + 1e-5f);
        float4 sk = *(const float4*)&g_skip[((size_t)tile * 64 + tk) * 128 + lane * 4];
        float4 o4;
        o4.x = (v.x - mu) * rs * lg4.x + lb4.x + sk.x;
        o4.y = (v.y - mu) * rs * lg4.y + lb4.y + sk.y;
        o4.z = (v.z - mu) * rs * lg4.z + lb4.z + sk.z;
        o4.w = (v.w - mu) * rs * lg4.w + lb4.w + sk.w;
        *(float4*)&Cs[tk * 132 + lane * 4] = o4;
    }
    __syncthreads();

    // transposed write: tile = b*64 + y, token-local = x -> out[b][c][y][x] contiguous in x
    int b = tile >> 6, y = tile & 63;
    for (int it = 0; it < 32; it++) {
        int idx = it * 256 + t;
        int c = idx >> 6, xcol = idx & 63;
        out[((size_t)(b * 128 + c) * 64 + y) * 64 + xcol] = Cs[xcol * 132 + c];
    }
}

// ---------------- launch ----------------
extern "C" void kernel_launch(void* const* d_in, const int* in_sizes, int n_in,
                              void* d_out, int out_size) {
    (void)in_sizes; (void)n_in; (void)out_size;
    const float* x      = (const float*)d_in[0];
    const float* qkv_w  = (const float*)d_in[1];
    const float* qkv_b  = (const float*)d_in[2];
    const float* proj_w = (const float*)d_in[3];
    const float* proj_b = (const float*)d_in[4];
    const float* mw1    = (const float*)d_in[5];
    const float* mb1    = (const float*)d_in[6];
    const float* mw2    = (const float*)d_in[7];
    const float* mb2    = (const float*)d_in[8];
    const float* tau    = (const float*)d_in[9];
    const float* ln1_g  = (const float*)d_in[10];
    const float* ln1_b  = (const float*)d_in[11];
    const float* ln2_g  = (const float*)d_in[12];
    const float* ln2_b  = (const float*)d_in[13];
    const float* ffn_w1 = (const float*)d_in[14];
    const float* ffn_b1 = (const float*)d_in[15];
    const float* ffn_w2 = (const float*)d_in[16];
    const float* ffn_b2 = (const float*)d_in[17];
    float* out = (float*)d_out;

    bias_kernel<<<16, 256>>>(mw1, mb1, mw2, mb2);
    gather_kernel<<<N_WIN, 256>>>(x);
    qkv_mma<<<dim3(N_WIN, 3), 256>>>(qkv_w, qkv_b);
    attn_kernel<<<8192, 128>>>(tau);
    proj_mma<<<N_WIN, 256>>>(x, proj_w, proj_b, ln1_g, ln1_b);
    ffn1_mma<<<dim3(N_WIN, 4), 256>>>(ffn_w1, ffn_b1);
    ffn2_mma<<<N_WIN, 256>>>(ffn_w2, ffn_b2, ln2_g, ln2_b, out);
}

// round 3
// speedup vs baseline: 2.7027x; 1.2520x over previous
#include <cuda_runtime.h>
#include <math.h>
#include <stdint.h>

// Problem constants: B=32, C=128, H=W=64, WS=8, SHIFT=4, HEADS=4, TOK=64, NW=64, DH=32, HID=512
#define N_WIN   2048      // B * NW
#define N_TOK   131072    // B * H * W

// ---------------- scratch (device globals; no allocation) ----------------
__device__ float g_xw[N_WIN * 64 * 128];     // rolled+windowed x, token-major
__device__ float g_q[8192 * 2048];           // [win*4+h][tok=64][d=32]
__device__ float g_k[8192 * 2048];
__device__ float g_v[8192 * 2048];
__device__ float g_attn[N_WIN * 64 * 128];   // [win][tok][c]
__device__ float g_skip[N_TOK * 128];        // [tokg][c]
__device__ float g_h1[N_TOK * 512];          // [tokg][hid]
__device__ float g_bias[4 * 64 * 64];        // [h][q][k]

// ---------------- tf32 mma helpers ----------------
__device__ __forceinline__ uint32_t f2tf32(float x) {
    uint32_t r;
    asm("cvt.rna.tf32.f32 %0, %1;" : "=r"(r) : "f"(x));
    return r;
}

__device__ __forceinline__ void mma8(float c[4], uint32_t a0, uint32_t a1, uint32_t a2, uint32_t a3,
                                     uint32_t b0, uint32_t b1) {
    asm volatile("mma.sync.aligned.m16n8k8.row.col.f32.tf32.tf32.f32 "
                 "{%0,%1,%2,%3},{%4,%5,%6,%7},{%8,%9},{%0,%1,%2,%3};"
                 : "+f"(c[0]), "+f"(c[1]), "+f"(c[2]), "+f"(c[3])
                 : "r"(a0), "r"(a1), "r"(a2), "r"(a3), "r"(b0), "r"(b1));
}

// Block tile: M=64, N=128, K-chunk=32. 8 warps = 4(M) x 2(N); warp tile 16x64.
template<int KTOT, int NTOT>
__device__ __forceinline__ void gemm64x128(const float* __restrict__ A,
                                           const float* __restrict__ W,
                                           int nbase,
                                           uint32_t* As, uint32_t* Bs,
                                           float acc[8][4], int t) {
    const int lane = t & 31, g = lane >> 2, tg = lane & 3;
    const int wm = (t >> 5) & 3, wn = t >> 7;
    const int m0w = wm * 16, n0w = wn * 64;

    for (int k0 = 0; k0 < KTOT; k0 += 32) {
        __syncthreads();
#pragma unroll
        for (int it = 0; it < 2; it++) {
            int p = it * 256 + t;
            int m = p >> 3, k4 = p & 7;
            float4 v = *(const float4*)&A[m * KTOT + k0 + k4 * 4];
            uint4 u = make_uint4(f2tf32(v.x), f2tf32(v.y), f2tf32(v.z), f2tf32(v.w));
            *(uint4*)&As[m * 36 + k4 * 4] = u;
        }
#pragma unroll
        for (int it = 0; it < 4; it++) {
            int p = it * 256 + t;
            int k = p >> 5, n4 = p & 31;
            float4 v = *(const float4*)&W[(size_t)(k0 + k) * NTOT + nbase + n4 * 4];
            uint4 u = make_uint4(f2tf32(v.x), f2tf32(v.y), f2tf32(v.z), f2tf32(v.w));
            *(uint4*)&Bs[k * 136 + n4 * 4] = u;
        }
        __syncthreads();
#pragma unroll
        for (int ks = 0; ks < 4; ks++) {
            int kk = ks * 8;
            uint32_t a0 = As[(m0w + g) * 36 + kk + tg];
            uint32_t a1 = As[(m0w + g + 8) * 36 + kk + tg];
            uint32_t a2 = As[(m0w + g) * 36 + kk + tg + 4];
            uint32_t a3 = As[(m0w + g + 8) * 36 + kk + tg + 4];
#pragma unroll
            for (int s = 0; s < 8; s++) {
                uint32_t b0 = Bs[(kk + tg) * 136 + n0w + s * 8 + g];
                uint32_t b1 = Bs[(kk + tg + 4) * 136 + n0w + s * 8 + g];
                mma8(acc[s], a0, a1, a2, a3, b0, b1);
            }
        }
    }
}

#define SMEM_BYTES 33792

// ---------------- 0. meta-MLP relative position bias ----------------
__global__ void bias_kernel(const float* __restrict__ w1, const float* __restrict__ b1,
                            const float* __restrict__ w2, const float* __restrict__ b2) {
    int p = blockIdx.x * 256 + threadIdx.x;
    int q = p >> 6, k = p & 63;
    float dy = (float)((q >> 3) - (k >> 3));
    float dx = (float)((q & 7) - (k & 7));
    float r0 = copysignf(log1pf(fabsf(dy)), dy);
    float r1 = copysignf(log1pf(fabsf(dx)), dx);
    float a0 = 0.f, a1 = 0.f, a2 = 0.f, a3 = 0.f;
    for (int j = 0; j < 256; j++) {
        float h = r0 * w1[j] + r1 * w1[256 + j] + b1[j];
        h = fmaxf(h, 0.f);
        a0 += h * w2[j * 4 + 0];
        a1 += h * w2[j * 4 + 1];
        a2 += h * w2[j * 4 + 2];
        a3 += h * w2[j * 4 + 3];
    }
    g_bias[0 * 4096 + p] = a0 + b2[0];
    g_bias[1 * 4096 + p] = a1 + b2[1];
    g_bias[2 * 4096 + p] = a2 + b2[2];
    g_bias[3 * 4096 + p] = a3 + b2[3];
}

// ---------------- 1. roll + window gather -> g_xw (token-major) ----------------
__global__ void __launch_bounds__(256) gather_kernel(const float* __restrict__ x) {
    __shared__ __align__(16) float Ts[64 * 132];
    int t = threadIdx.x;
    int win = blockIdx.x;
    int b = win >> 6, wy = (win >> 3) & 7, wx = win & 7;

    for (int it = 0; it < 8; it++) {
        int p = it * 256 + t;
        int c = p >> 4;
        int r = (p >> 1) & 7;
        int half = p & 1;
        int y = (wy * 8 + r + 4) & 63;
        int xb = (wx * 8 + 4 + half * 4) & 63;
        float4 v = *(const float4*)&x[((size_t)(b * 128 + c) * 64 + y) * 64 + xb];
        int tok = r * 8 + half * 4;
        Ts[(tok + 0) * 132 + c] = v.x;
        Ts[(tok + 1) * 132 + c] = v.y;
        Ts[(tok + 2) * 132 + c] = v.z;
        Ts[(tok + 3) * 132 + c] = v.w;
    }
    __syncthreads();
    float* dst = g_xw + (size_t)win * 64 * 128;
    for (int it = 0; it < 8; it++) {
        int p = it * 256 + t;
        int tok = p >> 5, c4 = p & 31;
        *(float4*)&dst[tok * 128 + c4 * 4] = *(const float4*)&Ts[tok * 132 + c4 * 4];
    }
}

// ---------------- 2. QKV GEMM (tf32 mma) ----------------
__global__ void __launch_bounds__(256) qkv_mma(const float* __restrict__ w,
                                               const float* __restrict__ qb) {
    __shared__ __align__(16) unsigned char smbuf[SMEM_BYTES];
    uint32_t* As = (uint32_t*)smbuf;
    uint32_t* Bs = As + 64 * 36;
    int t = threadIdx.x;
    int tile = blockIdx.x;
    int nby = blockIdx.y;

    float acc[8][4] = {};
    gemm64x128<128, 384>(g_xw + (size_t)tile * 64 * 128, w, nby * 128, As, Bs, acc, t);

    const int lane = t & 31, g = lane >> 2, tg = lane & 3;
    const int wm = (t >> 5) & 3, wn = t >> 7;
    const int m0w = wm * 16, n0w = wn * 64;
    float* dst = (nby == 0) ? g_q : (nby == 1) ? g_k : g_v;
#pragma unroll
    for (int s = 0; s < 8; s++) {
        int nl = n0w + s * 8 + 2 * tg;
        int head = nl >> 5, d = nl & 31;
        float b0v = qb[nby * 128 + nl], b1v = qb[nby * 128 + nl + 1];
        int m = m0w + g;
        float* base = &dst[((size_t)(tile * 4 + head) * 64 + m) * 32 + d];
        *(float2*)base = make_float2(acc[s][0] + b0v, acc[s][1] + b1v);
        *(float2*)(base + 8 * 32) = make_float2(acc[s][2] + b0v, acc[s][3] + b1v);
    }
}

// ---------------- 3. windowed attention (tf32 mma) ----------------
__global__ void __launch_bounds__(128) attn_mma(const float* __restrict__ tau) {
    __shared__ __align__(16) uint32_t Qs[64 * 36];   // tf32 [tok][36]
    __shared__ __align__(16) uint32_t Ks[64 * 36];
    __shared__ __align__(16) uint32_t Vs[64 * 36];
    __shared__ __align__(16) uint32_t Ps[64 * 68];   // tf32 probabilities
    __shared__ float qn[64], kn[64];
    __shared__ int   cnti[64];
    __shared__ float stau;

    int t = threadIdx.x;
    int wh = blockIdx.x;                 // win*4 + h
    int win = wh >> 2, h = wh & 3;
    int wy = (win >> 3) & 7, wx = win & 7;

    const float* qp = g_q + (size_t)wh * 2048;
    const float* kp = g_k + (size_t)wh * 2048;
    const float* vp = g_v + (size_t)wh * 2048;

    // load + tf32 convert
    for (int it = 0; it < 16; it++) {
        int idx = it * 128 + t;
        int tok = idx >> 5, d = idx & 31;
        Qs[tok * 36 + d] = f2tf32(qp[idx]);
        Ks[tok * 36 + d] = f2tf32(kp[idx]);
        Vs[tok * 36 + d] = f2tf32(vp[idx]);
    }
    if (t < 64) {
        int ys = wy * 8 + (t >> 3);
        int xs = wx * 8 + (t & 7);
        int ry = ys < 56 ? 0 : (ys < 60 ? 1 : 2);
        int rx = xs < 56 ? 0 : (xs < 60 ? 1 : 2);
        cnti[t] = ry * 3 + rx;
    }
    if (t == 0) stau = fmaxf(tau[h], 0.01f);
    // fp32 norms from global (L1/L2 hot)
    {
        const float* rp = (t < 64) ? (qp + t * 32) : (kp + (t - 64) * 32);
        float s = 0.f;
#pragma unroll
        for (int d4 = 0; d4 < 8; d4++) {
            float4 v = *(const float4*)&rp[d4 * 4];
            s += v.x * v.x + v.y * v.y + v.z * v.z + v.w * v.w;
        }
        float nv = sqrtf(s);
        if (t < 64) qn[t] = nv; else kn[t - 64] = nv;
    }
    __syncthreads();

    const int lane = t & 31, g = lane >> 2, tg = lane & 3;
    const int wid = t >> 5;
    const int m0 = wid * 16;
    const int r0 = m0 + g, r1 = r0 + 8;

    // ---- QK^T: 16x64, K=32 ----
    float acc[8][4] = {};
#pragma unroll
    for (int ks = 0; ks < 4; ks++) {
        int kk = ks * 8;
        uint32_t a0 = Qs[r0 * 36 + kk + tg];
        uint32_t a1 = Qs[r1 * 36 + kk + tg];
        uint32_t a2 = Qs[r0 * 36 + kk + tg + 4];
        uint32_t a3 = Qs[r1 * 36 + kk + tg + 4];
#pragma unroll
        for (int s = 0; s < 8; s++) {
            uint32_t b0 = Ks[(s * 8 + g) * 36 + kk + tg];
            uint32_t b1 = Ks[(s * 8 + g) * 36 + kk + tg + 4];
            mma8(acc[s], a0, a1, a2, a3, b0, b1);
        }
    }

    // ---- epilogue: cosine norm + tau + bias + mask ----
    float tv = stau;
    float iq0 = 1.f / qn[r0], iq1 = 1.f / qn[r1];   // qn>0 here; clamp handled below
    int mq0 = cnti[r0], mq1 = cnti[r1];
    const float* bias0 = &g_bias[h * 4096 + r0 * 64];
    const float* bias1 = &g_bias[h * 4096 + r1 * 64];
#pragma unroll
    for (int s = 0; s < 8; s++) {
        int c0 = s * 8 + 2 * tg;
        float kn0 = kn[c0], kn1 = kn[c0 + 1];
        float2 bA = *(const float2*)&bias0[c0];
        float2 bB = *(const float2*)&bias1[c0];
        int mk0 = cnti[c0], mk1 = cnti[c0 + 1];
        float d00 = fmaxf(qn[r0] * kn0, 1e-6f), d01 = fmaxf(qn[r0] * kn1, 1e-6f);
        float d10 = fmaxf(qn[r1] * kn0, 1e-6f), d11 = fmaxf(qn[r1] * kn1, 1e-6f);
        acc[s][0] = acc[s][0] / d00 / tv + bA.x + (mq0 != mk0 ? -100.f : 0.f);
        acc[s][1] = acc[s][1] / d01 / tv + bA.y + (mq0 != mk1 ? -100.f : 0.f);
        acc[s][2] = acc[s][2] / d10 / tv + bB.x + (mq1 != mk0 ? -100.f : 0.f);
        acc[s][3] = acc[s][3] / d11 / tv + bB.y + (mq1 != mk1 ? -100.f : 0.f);
    }
    (void)iq0; (void)iq1;

    // ---- softmax over rows r0, r1 (row lives in one quad: shfl 1,2) ----
    float mx0 = -1e30f, mx1 = -1e30f;
#pragma unroll
    for (int s = 0; s < 8; s++) {
        mx0 = fmaxf(mx0, fmaxf(acc[s][0], acc[s][1]));
        mx1 = fmaxf(mx1, fmaxf(acc[s][2], acc[s][3]));
    }
#pragma unroll
    for (int o = 1; o <= 2; o <<= 1) {
        mx0 = fmaxf(mx0, __shfl_xor_sync(0xffffffffu, mx0, o));
        mx1 = fmaxf(mx1, __shfl_xor_sync(0xffffffffu, mx1, o));
    }
    float sm0 = 0.f, sm1 = 0.f;
#pragma unroll
    for (int s = 0; s < 8; s++) {
        acc[s][0] = expf(acc[s][0] - mx0);
        acc[s][1] = expf(acc[s][1] - mx0);
        acc[s][2] = expf(acc[s][2] - mx1);
        acc[s][3] = expf(acc[s][3] - mx1);
        sm0 += acc[s][0] + acc[s][1];
        sm1 += acc[s][2] + acc[s][3];
    }
#pragma unroll
    for (int o = 1; o <= 2; o <<= 1) {
        sm0 += __shfl_xor_sync(0xffffffffu, sm0, o);
        sm1 += __shfl_xor_sync(0xffffffffu, sm1, o);
    }
    float inv0 = 1.f / sm0, inv1 = 1.f / sm1;
#pragma unroll
    for (int s = 0; s < 8; s++) {
        int c0 = s * 8 + 2 * tg;
        Ps[r0 * 68 + c0]     = f2tf32(acc[s][0] * inv0);
        Ps[r0 * 68 + c0 + 1] = f2tf32(acc[s][1] * inv0);
        Ps[r1 * 68 + c0]     = f2tf32(acc[s][2] * inv1);
        Ps[r1 * 68 + c0 + 1] = f2tf32(acc[s][3] * inv1);
    }
    __syncwarp();   // warp consumes only its own P rows

    // ---- P @ V: 16x32, K=64 ----
    float oacc[4][4] = {};
#pragma unroll
    for (int ks = 0; ks < 8; ks++) {
        int kk = ks * 8;
        uint32_t a0 = Ps[r0 * 68 + kk + tg];
        uint32_t a1 = Ps[r1 * 68 + kk + tg];
        uint32_t a2 = Ps[r0 * 68 + kk + tg + 4];
        uint32_t a3 = Ps[r1 * 68 + kk + tg + 4];
#pragma unroll
        for (int s2 = 0; s2 < 4; s2++) {
            uint32_t b0 = Vs[(kk + tg) * 36 + s2 * 8 + g];
            uint32_t b1 = Vs[(kk + tg + 4) * 36 + s2 * 8 + g];
            mma8(oacc[s2], a0, a1, a2, a3, b0, b1);
        }
    }

    // ---- write out [win][tok][h*32+d] ----
#pragma unroll
    for (int s2 = 0; s2 < 4; s2++) {
        int dc = s2 * 8 + 2 * tg;
        *(float2*)&g_attn[((size_t)win * 64 + r0) * 128 + h * 32 + dc] = make_float2(oacc[s2][0], oacc[s2][1]);
        *(float2*)&g_attn[((size_t)win * 64 + r1) * 128 + h * 32 + dc] = make_float2(oacc[s2][2], oacc[s2][3]);
    }
}

// ---------------- 4. proj (tf32 mma) + LN1 + residual -> g_skip ----------------
__global__ void __launch_bounds__(256) proj_mma(const float* __restrict__ x,
                                                const float* __restrict__ w,
                                                const float* __restrict__ pb,
                                                const float* __restrict__ lg,
                                                const float* __restrict__ lb) {
    __shared__ __align__(16) unsigned char smbuf[SMEM_BYTES];
    uint32_t* As = (uint32_t*)smbuf;
    uint32_t* Bs = As + 64 * 36;
    float* Cs = (float*)smbuf;
    int t = threadIdx.x;
    int win = blockIdx.x;
    int b = win >> 6, wy = (win >> 3) & 7, wx = win & 7;

    float acc[8][4] = {};
    gemm64x128<128, 128>(g_attn + (size_t)win * 64 * 128, w, 0, As, Bs, acc, t);

    const int lane = t & 31, g = lane >> 2, tg = lane & 3;
    const int wm = (t >> 5) & 3, wn = t >> 7;
    const int m0w = wm * 16, n0w = wn * 64;

    __syncthreads();
#pragma unroll
    for (int s = 0; s < 8; s++) {
        int c = n0w + s * 8 + 2 * tg;
        float b0v = pb[c], b1v = pb[c + 1];
        Cs[(m0w + g) * 132 + c]         = acc[s][0] + b0v;
        Cs[(m0w + g) * 132 + c + 1]     = acc[s][1] + b1v;
        Cs[(m0w + g + 8) * 132 + c]     = acc[s][2] + b0v;
        Cs[(m0w + g + 8) * 132 + c + 1] = acc[s][3] + b1v;
    }
    __syncthreads();

    int wrp = t >> 5;
    float4 lg4 = *(const float4*)&lg[lane * 4];
    float4 lb4 = *(const float4*)&lb[lane * 4];
    for (int i = 0; i < 8; i++) {
        int tk = wrp * 8 + i;
        float4 v = *(const float4*)&Cs[tk * 132 + lane * 4];
        float s  = v.x + v.y + v.z + v.w;
        float ss = v.x * v.x + v.y * v.y + v.z * v.z + v.w * v.w;
#pragma unroll
        for (int o = 16; o; o >>= 1) {
            s  += __shfl_xor_sync(0xffffffffu, s, o);
            ss += __shfl_xor_sync(0xffffffffu, ss, o);
        }
        float mu = s * (1.f / 128.f);
        float var = ss * (1.f / 128.f) - mu * mu;
        float rs = rsqrtf(var + 1e-5f);

        int y  = (wy * 8 + (tk >> 3) + 4) & 63;
        int xx = (wx * 8 + (tk & 7) + 4) & 63;
        const float* xr = x + ((size_t)(b * 128 + lane * 4) * 64 + y) * 64 + xx;
        float4 o4;
        o4.x = (v.x - mu) * rs * lg4.x + lb4.x + xr[0];
        o4.y = (v.y - mu) * rs * lg4.y + lb4.y + xr[4096];
        o4.z = (v.z - mu) * rs * lg4.z + lb4.z + xr[8192];
        o4.w = (v.w - mu) * rs * lg4.w + lb4.w + xr[12288];
        *(float4*)&g_skip[((size_t)b * 4096 + y * 64 + xx) * 128 + lane * 4] = o4;
    }
}

// ---------------- 5. FFN1 (tf32 mma) + GELU -> g_h1 ----------------
__global__ void __launch_bounds__(256) ffn1_mma(const float* __restrict__ w,
                                                const float* __restrict__ b1) {
    __shared__ __align__(16) unsigned char smbuf[SMEM_BYTES];
    uint32_t* As = (uint32_t*)smbuf;
    uint32_t* Bs = As + 64 * 36;
    int t = threadIdx.x;
    int tile = blockIdx.x;
    int nby = blockIdx.y;

    float acc[8][4] = {};
    gemm64x128<128, 512>(g_skip + (size_t)tile * 64 * 128, w, nby * 128, As, Bs, acc, t);

    const int lane = t & 31, g = lane >> 2, tg = lane & 3;
    const int wm = (t >> 5) & 3, wn = t >> 7;
    const int m0w = wm * 16, n0w = wn * 64;
#pragma unroll
    for (int s = 0; s < 8; s++) {
        int nl = n0w + s * 8 + 2 * tg;
        int ng = nby * 128 + nl;
        float b0v = b1[ng], b1v = b1[ng + 1];
        int m = m0w + g;
        float h0 = acc[s][0] + b0v, h1 = acc[s][1] + b1v;
        float h2 = acc[s][2] + b0v, h3 = acc[s][3] + b1v;
        h0 = 0.5f * h0 * (1.f + erff(h0 * 0.70710678118654752f));
        h1 = 0.5f * h1 * (1.f + erff(h1 * 0.70710678118654752f));
        h2 = 0.5f * h2 * (1.f + erff(h2 * 0.70710678118654752f));
        h3 = 0.5f * h3 * (1.f + erff(h3 * 0.70710678118654752f));
        float* base = &g_h1[((size_t)tile * 64 + m) * 512 + ng];
        *(float2*)base = make_float2(h0, h1);
        *(float2*)(base + 8 * 512) = make_float2(h2, h3);
    }
}

// ---------------- 6. FFN2 (tf32 mma, K=512) + LN2 + residual -> out ----------------
__global__ void __launch_bounds__(256) ffn2_mma(const float* __restrict__ w,
                                                const float* __restrict__ b2,
                                                const float* __restrict__ lg,
                                                const float* __restrict__ lb,
                                                float* __restrict__ out) {
    __shared__ __align__(16) unsigned char smbuf[SMEM_BYTES];
    uint32_t* As = (uint32_t*)smbuf;
    uint32_t* Bs = As + 64 * 36;
    float* Cs = (float*)smbuf;
    int t = threadIdx.x;
    int tile = blockIdx.x;

    float acc[8][4] = {};
    gemm64x128<512, 128>(g_h1 + (size_t)tile * 64 * 512, w, 0, As, Bs, acc, t);

    const int lane = t & 31, g = lane >> 2, tg = lane & 3;
    const int wm = (t >> 5) & 3, wn = t >> 7;
    const int m0w = wm * 16, n0w = wn * 64;

    __syncthreads();
#pragma unroll
    for (int s = 0; s < 8; s++) {
        int c = n0w + s * 8 + 2 * tg;
        float b0v = b2[c], b1v = b2[c + 1];
        Cs[(m0w + g) * 132 + c]         = acc[s][0] + b0v;
        Cs[(m0w + g) * 132 + c + 1]     = acc[s][1] + b1v;
        Cs[(m0w + g + 8) * 132 + c]     = acc[s][2] + b0v;
        Cs[(m0w + g + 8) * 132 + c + 1] = acc[s][3] + b1v;
    }
    __syncthreads();

    int wrp = t >> 5;
    float4 lg4 = *(const float4*)&lg[lane * 4];
    float4 lb4 = *(const float4*)&lb[lane * 4];
    for (int i = 0; i < 8; i++) {
        int tk = wrp * 8 + i;
        float4 v = *(const float4*)&Cs[tk * 132 + lane * 4];
        float s  = v.x + v.y + v.z + v.w;
        float ss = v.x * v.x + v.y * v.y + v.z * v.z + v.w * v.w;
#pragma unroll
        for (int o = 16; o; o >>= 1) {
            s  += __shfl_xor_sync(0xffffffffu, s, o);
            ss += __shfl_xor_sync(0xffffffffu, ss, o);
        }
        float mu = s * (1.f / 128.f);
        float var = ss * (1.f / 128.f) - mu * mu;
        float rs = rsqrtf(var + 1e-5f);
        float4 sk = *(const float4*)&g_skip[((size_t)tile * 64 + tk) * 128 + lane * 4];
        float4 o4;
        o4.x = (v.x - mu) * rs * lg4.x + lb4.x + sk.x;
        o4.y = (v.y - mu) * rs * lg4.y + lb4.y + sk.y;
        o4.z = (v.z - mu) * rs * lg4.z + lb4.z + sk.z;
        o4.w = (v.w - mu) * rs * lg4.w + lb4.w + sk.w;
        *(float4*)&Cs[tk * 132 + lane * 4] = o4;
    }
    __syncthreads();

    int b = tile >> 6, y = tile & 63;
    for (int it = 0; it < 32; it++) {
        int idx = it * 256 + t;
        int c = idx >> 6, xcol = idx & 63;
        out[((size_t)(b * 128 + c) * 64 + y) * 64 + xcol] = Cs[xcol * 132 + c];
    }
}

// ---------------- launch ----------------
extern "C" void kernel_launch(void* const* d_in, const int* in_sizes, int n_in,
                              void* d_out, int out_size) {
    (void)in_sizes; (void)n_in; (void)out_size;
    const float* x      = (const float*)d_in[0];
    const float* qkv_w  = (const float*)d_in[1];
    const float* qkv_b  = (const float*)d_in[2];
    const float* proj_w = (const float*)d_in[3];
    const float* proj_b = (const float*)d_in[4];
    const float* mw1    = (const float*)d_in[5];
    const float* mb1    = (const float*)d_in[6];
    const float* mw2    = (const float*)d_in[7];
    const float* mb2    = (const float*)d_in[8];
    const float* tau    = (const float*)d_in[9];
    const float* ln1_g  = (const float*)d_in[10];
    const float* ln1_b  = (const float*)d_in[11];
    const float* ln2_g  = (const float*)d_in[12];
    const float* ln2_b  = (const float*)d_in[13];
    const float* ffn_w1 = (const float*)d_in[14];
    const float* ffn_b1 = (const float*)d_in[15];
    const float* ffn_w2 = (const float*)d_in[16];
    const float* ffn_b2 = (const float*)d_in[17];
    float* out = (float*)d_out;

    bias_kernel<<<16, 256>>>(mw1, mb1, mw2, mb2);
    gather_kernel<<<N_WIN, 256>>>(x);
    qkv_mma<<<dim3(N_WIN, 3), 256>>>(qkv_w, qkv_b);
    attn_mma<<<8192, 128>>>(tau);
    proj_mma<<<N_WIN, 256>>>(x, proj_w, proj_b, ln1_g, ln1_b);
    ffn1_mma<<<dim3(N_WIN, 4), 256>>>(ffn_w1, ffn_b1);
    ffn2_mma<<<N_WIN, 256>>>(ffn_w2, ffn_b2, ln2_g, ln2_b, out);
}